// round 1
// baseline (speedup 1.0000x reference)
#include <cuda_runtime.h>
#include <cuda_bf16.h>
#include <mma.h>
#include <cstdint>
#include <cstddef>
#include <type_traits>

using namespace nvcuda;

#define BATCH 8
#define CCH   512
#define NPIX  4096
#define CQD   64

// ---------------- static scratch (no runtime allocation allowed) ----------------
__device__ __nv_bfloat16 g_xb[(size_t)BATCH * CCH * NPIX];     // x in bf16
__device__ __nv_bfloat16 g_Wq[CQD * CCH];
__device__ __nv_bfloat16 g_Wk[CQD * CCH];
__device__ __nv_bfloat16 g_Wv[CCH * CCH];
__device__ __nv_bfloat16 g_q[(size_t)BATCH * CQD * NPIX];
__device__ __nv_bfloat16 g_k[(size_t)BATCH * CQD * NPIX];
__device__ __nv_bfloat16 g_v[(size_t)BATCH * CCH * NPIX];
__device__ float         g_scores[(size_t)BATCH * NPIX * NPIX]; // 536 MB
__device__ __nv_bfloat16 g_attn[(size_t)BATCH * NPIX * NPIX];   // 268 MB

// ---------------- fp32 -> bf16 cast (vectorized) ----------------
__global__ void cast_kernel(const float* __restrict__ in,
                            __nv_bfloat16* __restrict__ out, size_t n4) {
    size_t i = (size_t)blockIdx.x * blockDim.x + threadIdx.x;
    if (i < n4) {
        float4 f = reinterpret_cast<const float4*>(in)[i];
        __nv_bfloat162 a = __floats2bfloat162_rn(f.x, f.y);
        __nv_bfloat162 b = __floats2bfloat162_rn(f.z, f.w);
        uint2 u;
        u.x = *reinterpret_cast<unsigned*>(&a);
        u.y = *reinterpret_cast<unsigned*>(&b);
        reinterpret_cast<uint2*>(out)[i] = u;
    }
}

// ---------------- generic bf16 wmma GEMM ----------------
// C[M,N] = A (MxK) * B (KxN), fp32 accumulate.
// AROW: A row-major (lda=K-stride). !AROW: A col-major, A[m][k] = A[k*lda + m].
// BROW: B row-major. !BROW: B col-major, B[k][n] = B[n*ldb + k].
// EPI 0: fp32 plain store
// EPI 1: bf16 store of (acc + bias[row])
// EPI 2: fp32 store of (gamma[0]*acc + xres[same offset])
template<int BM, int BN, int BK, int WM, int WN, bool AROW, bool BROW, int EPI>
__global__ void __launch_bounds__((BM / WM) * (BN / WN) * 32)
gemm_bf16(const __nv_bfloat16* __restrict__ A, size_t strideA, int lda,
          const __nv_bfloat16* __restrict__ Bm, size_t strideB, int ldb,
          void* __restrict__ Cm, size_t strideC, int ldc,
          const float* __restrict__ bias,
          const float* __restrict__ gamma,
          const float* __restrict__ xres, size_t strideX,
          int M, int N, int K)
{
    constexpr int WGM = BM / WM, WGN = BN / WN, NW = WGM * WGN;
    constexpr int MI = WM / 16, NI = WN / 16;
    constexpr int SA_R = AROW ? BM : BK, SA_C = AROW ? BK : BM;
    constexpr int SB_R = BROW ? BK : BN, SB_C = BROW ? BN : BK;

    __shared__ __nv_bfloat16 smA[SA_R][SA_C + 8];
    __shared__ __nv_bfloat16 smB[SB_R][SB_C + 8];
    __shared__ float stage[NW][16 * 16];

    const int b = blockIdx.z;
    const __nv_bfloat16* Ab = A + strideA * (size_t)b;
    const __nv_bfloat16* Bb = Bm + strideB * (size_t)b;
    const size_t cb = strideC * (size_t)b;

    const int blockM = blockIdx.y * BM;
    const int blockN = blockIdx.x * BN;
    const int tid = threadIdx.x;
    const int wid = tid >> 5, lane = tid & 31;
    const int wm0 = (wid % WGM) * WM;
    const int wn0 = (wid / WGM) * WN;

    using ALayout = typename std::conditional<AROW, wmma::row_major, wmma::col_major>::type;
    using BLayout = typename std::conditional<BROW, wmma::row_major, wmma::col_major>::type;

    wmma::fragment<wmma::accumulator, 16, 16, 16, float> acc[MI][NI];
#pragma unroll
    for (int i = 0; i < MI; i++)
#pragma unroll
        for (int j = 0; j < NI; j++) wmma::fill_fragment(acc[i][j], 0.0f);

    for (int k0 = 0; k0 < K; k0 += BK) {
        // ---- stage A tile ----
        {
            constexpr int CV = SA_C / 8;
            constexpr int IT = (SA_R * CV) / (NW * 32);
            static_assert((SA_R * CV) % (NW * 32) == 0, "A copy div");
#pragma unroll
            for (int it = 0; it < IT; ++it) {
                int idx = tid + it * NW * 32;
                int r = idx / CV, cv = idx % CV;
                const __nv_bfloat16* src = AROW
                    ? Ab + (size_t)(blockM + r) * lda + k0 + cv * 8
                    : Ab + (size_t)(k0 + r) * lda + blockM + cv * 8;
                *reinterpret_cast<uint4*>(&smA[r][cv * 8]) =
                    *reinterpret_cast<const uint4*>(src);
            }
        }
        // ---- stage B tile ----
        {
            constexpr int CV = SB_C / 8;
            constexpr int IT = (SB_R * CV) / (NW * 32);
            static_assert((SB_R * CV) % (NW * 32) == 0, "B copy div");
#pragma unroll
            for (int it = 0; it < IT; ++it) {
                int idx = tid + it * NW * 32;
                int r = idx / CV, cv = idx % CV;
                const __nv_bfloat16* src = BROW
                    ? Bb + (size_t)(k0 + r) * ldb + blockN + cv * 8
                    : Bb + (size_t)(blockN + r) * ldb + k0 + cv * 8;
                *reinterpret_cast<uint4*>(&smB[r][cv * 8]) =
                    *reinterpret_cast<const uint4*>(src);
            }
        }
        __syncthreads();

#pragma unroll
        for (int kk = 0; kk < BK; kk += 16) {
            wmma::fragment<wmma::matrix_a, 16, 16, 16, __nv_bfloat16, ALayout> af[MI];
            wmma::fragment<wmma::matrix_b, 16, 16, 16, __nv_bfloat16, BLayout> bfr[NI];
#pragma unroll
            for (int i = 0; i < MI; i++) {
                const __nv_bfloat16* p = AROW ? &smA[wm0 + i * 16][kk]
                                              : &smA[kk][wm0 + i * 16];
                wmma::load_matrix_sync(af[i], p, SA_C + 8);
            }
#pragma unroll
            for (int j = 0; j < NI; j++) {
                const __nv_bfloat16* p = BROW ? &smB[kk][wn0 + j * 16]
                                              : &smB[wn0 + j * 16][kk];
                wmma::load_matrix_sync(bfr[j], p, SB_C + 8);
            }
#pragma unroll
            for (int i = 0; i < MI; i++)
#pragma unroll
                for (int j = 0; j < NI; j++)
                    wmma::mma_sync(acc[i][j], af[i], bfr[j], acc[i][j]);
        }
        __syncthreads();
    }

    // ---- epilogue via per-warp staging ----
    float gval = 0.0f;
    if (EPI == 2) gval = gamma[0];

#pragma unroll
    for (int i = 0; i < MI; i++) {
#pragma unroll
        for (int j = 0; j < NI; j++) {
            wmma::store_matrix_sync(&stage[wid][0], acc[i][j], 16, wmma::mem_row_major);
            __syncwarp();
            int rowBase = blockM + wm0 + i * 16;
            int colBase = blockN + wn0 + j * 16;
#pragma unroll
            for (int e = lane; e < 256; e += 32) {
                int r = e >> 4, c = e & 15;
                float val = stage[wid][e];
                size_t o = (size_t)(rowBase + r) * ldc + colBase + c;
                if (EPI == 0) {
                    ((float*)Cm)[cb + o] = val;
                } else if (EPI == 1) {
                    ((__nv_bfloat16*)Cm)[cb + o] = __float2bfloat16(val + bias[rowBase + r]);
                } else {
                    ((float*)Cm)[cb + o] = gval * val + xres[strideX * (size_t)b + o];
                }
            }
            __syncwarp();
        }
    }
}

// ---------------- row softmax: fp32 scores -> bf16 probs ----------------
__global__ void softmax_kernel(const float* __restrict__ s,
                               __nv_bfloat16* __restrict__ p) {
    size_t row = blockIdx.x;  // b*NPIX + i
    const float4* src = reinterpret_cast<const float4*>(s + row * NPIX);
    uint2* dst = reinterpret_cast<uint2*>(p + row * NPIX);
    int t = threadIdx.x;

    float4 v[4];
    float mx = -1e30f;
#pragma unroll
    for (int i = 0; i < 4; i++) {
        v[i] = src[i * 256 + t];
        mx = fmaxf(mx, fmaxf(fmaxf(v[i].x, v[i].y), fmaxf(v[i].z, v[i].w)));
    }
    __shared__ float red[8];
#pragma unroll
    for (int o = 16; o > 0; o >>= 1) mx = fmaxf(mx, __shfl_xor_sync(0xffffffffu, mx, o));
    if ((t & 31) == 0) red[t >> 5] = mx;
    __syncthreads();
    float bmax = red[0];
#pragma unroll
    for (int w = 1; w < 8; w++) bmax = fmaxf(bmax, red[w]);
    __syncthreads();

    float e[16];
    float sum = 0.0f;
#pragma unroll
    for (int i = 0; i < 4; i++) {
        e[i * 4 + 0] = __expf(v[i].x - bmax);
        e[i * 4 + 1] = __expf(v[i].y - bmax);
        e[i * 4 + 2] = __expf(v[i].z - bmax);
        e[i * 4 + 3] = __expf(v[i].w - bmax);
        sum += e[i * 4 + 0] + e[i * 4 + 1] + e[i * 4 + 2] + e[i * 4 + 3];
    }
#pragma unroll
    for (int o = 16; o > 0; o >>= 1) sum += __shfl_xor_sync(0xffffffffu, sum, o);
    if ((t & 31) == 0) red[t >> 5] = sum;
    __syncthreads();
    float tot = 0.0f;
#pragma unroll
    for (int w = 0; w < 8; w++) tot += red[w];
    float inv = 1.0f / tot;

#pragma unroll
    for (int i = 0; i < 4; i++) {
        __nv_bfloat162 h0 = __floats2bfloat162_rn(e[i * 4 + 0] * inv, e[i * 4 + 1] * inv);
        __nv_bfloat162 h1 = __floats2bfloat162_rn(e[i * 4 + 2] * inv, e[i * 4 + 3] * inv);
        uint2 u;
        u.x = *reinterpret_cast<unsigned*>(&h0);
        u.y = *reinterpret_cast<unsigned*>(&h1);
        dst[i * 256 + t] = u;
    }
}

// ---------------- launch ----------------
extern "C" void kernel_launch(void* const* d_in, const int* in_sizes, int n_in,
                              void* d_out, int out_size) {
    const float* x     = (const float*)d_in[0];
    const float* Wq    = (const float*)d_in[1];
    const float* bq    = (const float*)d_in[2];
    const float* Wk    = (const float*)d_in[3];
    const float* bk    = (const float*)d_in[4];
    const float* Wv    = (const float*)d_in[5];
    const float* bv    = (const float*)d_in[6];
    const float* gamma = (const float*)d_in[7];

    __nv_bfloat16 *xb, *wq, *wk, *wv, *q, *k, *v, *attn;
    float* scores;
    cudaGetSymbolAddress((void**)&xb, g_xb);
    cudaGetSymbolAddress((void**)&wq, g_Wq);
    cudaGetSymbolAddress((void**)&wk, g_Wk);
    cudaGetSymbolAddress((void**)&wv, g_Wv);
    cudaGetSymbolAddress((void**)&q, g_q);
    cudaGetSymbolAddress((void**)&k, g_k);
    cudaGetSymbolAddress((void**)&v, g_v);
    cudaGetSymbolAddress((void**)&scores, g_scores);
    cudaGetSymbolAddress((void**)&attn, g_attn);

    const size_t sX = (size_t)CCH * NPIX;   // per-batch x/v/out stride
    const size_t sQ = (size_t)CQD * NPIX;   // per-batch q/k stride
    const size_t sS = (size_t)NPIX * NPIX;  // per-batch scores/attn stride

    // casts
    {
        size_t n4 = (size_t)BATCH * sX / 4;
        cast_kernel<<<(unsigned)((n4 + 255) / 256), 256>>>(x, xb, n4);
        size_t nq4 = (size_t)CQD * CCH / 4;
        cast_kernel<<<(unsigned)((nq4 + 255) / 256), 256>>>(Wq, wq, nq4);
        cast_kernel<<<(unsigned)((nq4 + 255) / 256), 256>>>(Wk, wk, nq4);
        size_t nv4 = (size_t)CCH * CCH / 4;
        cast_kernel<<<(unsigned)((nv4 + 255) / 256), 256>>>(Wv, wv, nv4);
    }

    // q = Wq @ xb + bq   [64 x 4096] per batch, bf16 out
    {
        dim3 g(NPIX / 128, CQD / 64, BATCH);
        gemm_bf16<64, 128, 64, 32, 32, true, true, 1><<<g, 256>>>(
            wq, 0, CCH, xb, sX, NPIX, q, sQ, NPIX, bq, nullptr, nullptr, 0,
            CQD, NPIX, CCH);
        gemm_bf16<64, 128, 64, 32, 32, true, true, 1><<<g, 256>>>(
            wk, 0, CCH, xb, sX, NPIX, k, sQ, NPIX, bk, nullptr, nullptr, 0,
            CQD, NPIX, CCH);
    }

    // v = Wv @ xb + bv   [512 x 4096] per batch, bf16 out
    {
        dim3 g(NPIX / 128, CCH / 128, BATCH);
        gemm_bf16<128, 128, 64, 64, 32, true, true, 1><<<g, 256>>>(
            wv, 0, CCH, xb, sX, NPIX, v, sX, NPIX, bv, nullptr, nullptr, 0,
            CCH, NPIX, CCH);
    }

    // scores[i,j] = sum_d q[d,i]*k[d,j]  -> fp32 [4096 x 4096] per batch
    {
        dim3 g(NPIX / 128, NPIX / 128, BATCH);
        gemm_bf16<128, 128, 64, 64, 32, false, true, 0><<<g, 256>>>(
            q, sQ, NPIX, k, sQ, NPIX, scores, sS, NPIX, nullptr, nullptr,
            nullptr, 0, NPIX, NPIX, CQD);
    }

    // softmax rows -> bf16 attn
    softmax_kernel<<<BATCH * NPIX, 256>>>(scores, attn);

    // out[c,i] = gamma * sum_j v[c,j]*attn[i,j] + x[c,i]  -> d_out fp32
    {
        dim3 g(NPIX / 128, CCH / 128, BATCH);
        gemm_bf16<128, 128, 64, 64, 32, true, false, 2><<<g, 256>>>(
            v, sX, NPIX, attn, sS, NPIX, d_out, sX, NPIX, nullptr, gamma,
            x, sX, CCH, NPIX, NPIX);
    }
}